// round 8
// baseline (speedup 1.0000x reference)
#include <cuda_runtime.h>
#include <math.h>

#define T_DIM 512
#define B_DIM 64
#define I_DIM 1024
#define H_DIM 2048
#define TB (T_DIM * B_DIM)
#define NB 148          // persistent grid: one block per SM, all co-resident
#define NT 256

// ---- static device scratch (no allocations allowed) ----
__device__ float g_XZ[(size_t)TB * H_DIM];   // X @ W_xz + b_z
__device__ float g_XR[(size_t)TB * H_DIM];   // X @ W_xr + b_r
__device__ float g_XH[(size_t)TB * H_DIM];   // X @ W_xh + b_h
__device__ float g_H[2][B_DIM * H_DIM];      // ping-pong hidden state
__device__ float g_Z[B_DIM * H_DIM];         // update gate
__device__ float g_RH[B_DIM * H_DIM];        // R * H
__device__ unsigned g_bar_cnt = 0;           // grid-barrier arrivals (reset per launch)

// ============================================================
// Precompute: out[g][(t*B+b)][j] = X[t,b,:] @ W_xg[:,j] + b_g[j]
// A: (TB x I), W: (I x H_DIM). 64x64 tile, 256 thr, 4x4/thread.
// Bias is added HERE ONLY (recurrent epilogues must not re-add it).
// ============================================================
__global__ void xproj_kernel(const float* __restrict__ X,
                             const float* __restrict__ Wz,
                             const float* __restrict__ Wr,
                             const float* __restrict__ Wh,
                             const float* __restrict__ bz,
                             const float* __restrict__ br,
                             const float* __restrict__ bh)
{
    const float* W;
    const float* bias;
    float* out;
    int g = blockIdx.z;
    if (g == 0)      { W = Wz; bias = bz; out = g_XZ; }
    else if (g == 1) { W = Wr; bias = br; out = g_XR; }
    else             { W = Wh; bias = bh; out = g_XH; }

    int n0 = blockIdx.x * 64;
    int m0 = blockIdx.y * 64;

    __shared__ float As[16][64];
    __shared__ float Bs[16][64];

    int tid = threadIdx.x;
    int tx = tid & 15;
    int ty = tid >> 4;

    float acc[4][4];
#pragma unroll
    for (int i = 0; i < 4; i++)
#pragma unroll
        for (int j = 0; j < 4; j++) acc[i][j] = 0.0f;

    int a_m = tid >> 2;          // 0..63
    int a_k = (tid & 3) * 4;     // 0,4,8,12
    int b_k = tid >> 4;          // 0..15
    int b_n = (tid & 15) * 4;    // 0..60

    for (int k0 = 0; k0 < I_DIM; k0 += 16) {
        float4 av = *(const float4*)&X[(size_t)(m0 + a_m) * I_DIM + k0 + a_k];
        As[a_k + 0][a_m] = av.x;
        As[a_k + 1][a_m] = av.y;
        As[a_k + 2][a_m] = av.z;
        As[a_k + 3][a_m] = av.w;
        float4 bv = *(const float4*)&W[(size_t)(k0 + b_k) * H_DIM + n0 + b_n];
        Bs[b_k][b_n + 0] = bv.x;
        Bs[b_k][b_n + 1] = bv.y;
        Bs[b_k][b_n + 2] = bv.z;
        Bs[b_k][b_n + 3] = bv.w;
        __syncthreads();
#pragma unroll
        for (int k = 0; k < 16; k++) {
            float a[4], b[4];
#pragma unroll
            for (int i = 0; i < 4; i++) a[i] = As[k][ty * 4 + i];
#pragma unroll
            for (int j = 0; j < 4; j++) b[j] = Bs[k][tx * 4 + j];
#pragma unroll
            for (int i = 0; i < 4; i++)
#pragma unroll
                for (int j = 0; j < 4; j++) acc[i][j] += a[i] * b[j];
        }
        __syncthreads();
    }

#pragma unroll
    for (int i = 0; i < 4; i++) {
        int m = m0 + ty * 4 + i;
#pragma unroll
        for (int j = 0; j < 4; j++) {
            int n = n0 + tx * 4 + j;
            out[(size_t)m * H_DIM + n] = acc[i][j] + bias[n];
        }
    }
}

// ============================================================
// Grid-wide barrier: monotonically increasing arrivals counter.
// No reset inside the kernel (avoids the classic reset race);
// host memsets g_bar_cnt to 0 once per launch.
// ============================================================
__device__ __forceinline__ void grid_sync(unsigned target)
{
    __syncthreads();
    if (threadIdx.x == 0) {
        __threadfence();                       // release all prior writes
        atomicAdd(&g_bar_cnt, 1u);
        unsigned v;
        do {
            asm volatile("ld.global.acquire.gpu.u32 %0, [%1];"
                         : "=r"(v) : "l"(&g_bar_cnt));
        } while (v < target);
    }
    __syncthreads();
}

// ============================================================
// 64 x 32 x 2048 fp32 GEMM tile into registers.
// acc[4][2] += A(64 x K) @ W(K x N) cols [n0, n0+32).
// 256 threads; thread (ty,tx) owns rows ty*4..+3, cols n0+tx*2..+1.
// ============================================================
__device__ __forceinline__ void step_gemm(const float* __restrict__ A,
                                          const float* __restrict__ W,
                                          int N, int n0, int tid,
                                          float acc[4][2])
{
    __shared__ float Hs[16][64];
    __shared__ float Ws[16][32];

    int tx = tid & 15;
    int ty = tid >> 4;

    int h_b = tid >> 2;          // 0..63
    int h_k = (tid & 3) * 4;     // 0,4,8,12
    int w_k = tid >> 4;          // 0..15
    int w_n = (tid & 15) * 2;    // 0..30

    for (int k0 = 0; k0 < H_DIM; k0 += 16) {
        float4 hv = *(const float4*)&A[(size_t)h_b * H_DIM + k0 + h_k];
        Hs[h_k + 0][h_b] = hv.x;
        Hs[h_k + 1][h_b] = hv.y;
        Hs[h_k + 2][h_b] = hv.z;
        Hs[h_k + 3][h_b] = hv.w;
        float2 wv = *(const float2*)&W[(size_t)(k0 + w_k) * N + n0 + w_n];
        Ws[w_k][w_n + 0] = wv.x;
        Ws[w_k][w_n + 1] = wv.y;
        __syncthreads();
#pragma unroll
        for (int k = 0; k < 16; k++) {
            float a[4], b[2];
#pragma unroll
            for (int i = 0; i < 4; i++) a[i] = Hs[k][ty * 4 + i];
#pragma unroll
            for (int j = 0; j < 2; j++) b[j] = Ws[k][tx * 2 + j];
#pragma unroll
            for (int i = 0; i < 4; i++)
#pragma unroll
                for (int j = 0; j < 2; j++) acc[i][j] += a[i] * b[j];
        }
        __syncthreads();
    }
}

// ============================================================
// Persistent recurrence kernel. grid = NB blocks (all resident).
// Per step:
//   P1 (blocks 0..127): Z = sigmoid(XZ + H@Whz); RH = sigmoid(XR + H@Whr)*H
//   barrier
//   P2 (blocks 0..63):  Hnew = Z*H + (1-Z)*tanh(XH + RH@Whh)
//      (blocks 64..95): Y[t-1] = H@Whq + b_hq   (H here == Hnew of t-1)
//   barrier
// Final: Y[T-1] and optional H_final copy.
// ============================================================
__global__ void __launch_bounds__(NT, 1)
gru_persistent(const float* __restrict__ Whz,
               const float* __restrict__ Whr,
               const float* __restrict__ Whh,
               const float* __restrict__ Whq,
               const float* __restrict__ bq,
               float* __restrict__ out,
               int write_hfinal)
{
    const int blk = blockIdx.x;
    const int tid = threadIdx.x;
    const int tx = tid & 15;
    const int ty = tid >> 4;
    unsigned epoch = 0;

    for (int t = 0; t < T_DIM; ++t) {
        const float* Hold = g_H[t & 1];
        float* Hnew = g_H[(t + 1) & 1];

        // ---------------- P1: gates Z and R ----------------
        if (blk < 128) {
            const int gate = blk >> 6;            // 0: Z, 1: R
            const int n0 = (blk & 63) * 32;
            const float* W  = gate ? Whr  : Whz;
            const float* Xp = gate ? g_XR : g_XZ;

            float acc[4][2] = {{0.f,0.f},{0.f,0.f},{0.f,0.f},{0.f,0.f}};
            step_gemm(Hold, W, H_DIM, n0, tid, acc);

#pragma unroll
            for (int i = 0; i < 4; i++) {
                int b = ty * 4 + i;
#pragma unroll
                for (int j = 0; j < 2; j++) {
                    int c = n0 + tx * 2 + j;
                    float x = Xp[(size_t)(t * B_DIM + b) * H_DIM + c] + acc[i][j];
                    float s = 1.0f / (1.0f + expf(-x));
                    if (gate) g_RH[b * H_DIM + c] = s * Hold[b * H_DIM + c];
                    else      g_Z[b * H_DIM + c]  = s;
                }
            }
        }
        epoch++; grid_sync(epoch * NB);

        // ---------------- P2: Hnew and Y[t-1] ----------------
        if (blk < 64) {
            const int n0 = blk * 32;
            float acc[4][2] = {{0.f,0.f},{0.f,0.f},{0.f,0.f},{0.f,0.f}};
            step_gemm(g_RH, Whh, H_DIM, n0, tid, acc);

#pragma unroll
            for (int i = 0; i < 4; i++) {
                int b = ty * 4 + i;
#pragma unroll
                for (int j = 0; j < 2; j++) {
                    int c = n0 + tx * 2 + j;
                    float ht = tanhf(g_XH[(size_t)(t * B_DIM + b) * H_DIM + c] + acc[i][j]);
                    float z = g_Z[b * H_DIM + c];
                    Hnew[b * H_DIM + c] = z * Hold[b * H_DIM + c] + (1.0f - z) * ht;
                }
            }
        } else if (blk < 96 && t > 0) {
            const int n0 = (blk - 64) * 32;
            float acc[4][2] = {{0.f,0.f},{0.f,0.f},{0.f,0.f},{0.f,0.f}};
            step_gemm(Hold, Whq, I_DIM, n0, tid, acc);

#pragma unroll
            for (int i = 0; i < 4; i++) {
                int b = ty * 4 + i;
#pragma unroll
                for (int j = 0; j < 2; j++) {
                    int c = n0 + tx * 2 + j;
                    out[(size_t)((t - 1) * B_DIM + b) * I_DIM + c] = acc[i][j] + bq[c];
                }
            }
        }
        epoch++; grid_sync(epoch * NB);
    }

    // ---------------- tail: Y[T-1] and H_final ----------------
    const float* Hfin = g_H[T_DIM & 1];   // T even -> g_H[0]
    if (blk < 32) {
        const int n0 = blk * 32;
        float acc[4][2] = {{0.f,0.f},{0.f,0.f},{0.f,0.f},{0.f,0.f}};
        step_gemm(Hfin, Whq, I_DIM, n0, tid, acc);
#pragma unroll
        for (int i = 0; i < 4; i++) {
            int b = ty * 4 + i;
#pragma unroll
            for (int j = 0; j < 2; j++) {
                int c = n0 + tx * 2 + j;
                out[(size_t)((T_DIM - 1) * B_DIM + b) * I_DIM + c] = acc[i][j] + bq[c];
            }
        }
    } else if (blk >= 32 && blk < 64 && write_hfinal) {
        // copy H_final (B_DIM*H_DIM = 131072 floats) after output Ys
        float* dst = out + (size_t)TB * I_DIM;
        int base = ((blk - 32) * NT + tid) * 16;   // 32*256*16 = 131072
#pragma unroll
        for (int v = 0; v < 4; v++) {
            *(float4*)&dst[base + v * 4] = *(const float4*)&Hfin[base + v * 4];
        }
    }
}

extern "C" void kernel_launch(void* const* d_in, const int* in_sizes, int n_in,
                              void* d_out, int out_size)
{
    (void)in_sizes; (void)n_in;
    const float* inputs = (const float*)d_in[0];
    const float* state  = (const float*)d_in[1];
    const float* W_xz   = (const float*)d_in[2];
    const float* W_hz   = (const float*)d_in[3];
    const float* b_z    = (const float*)d_in[4];
    const float* W_xr   = (const float*)d_in[5];
    const float* W_hr   = (const float*)d_in[6];
    const float* b_r    = (const float*)d_in[7];
    const float* W_xh   = (const float*)d_in[8];
    const float* W_hh   = (const float*)d_in[9];
    const float* b_h    = (const float*)d_in[10];
    const float* W_hq   = (const float*)d_in[11];
    const float* b_hq   = (const float*)d_in[12];
    float* out = (float*)d_out;

    float* hbuf = nullptr;
    cudaGetSymbolAddress((void**)&hbuf, g_H);
    unsigned* barp = nullptr;
    cudaGetSymbolAddress((void**)&barp, g_bar_cnt);

    // reset barrier counter + initial state -> g_H[0]
    cudaMemsetAsync(barp, 0, sizeof(unsigned), 0);
    cudaMemcpyAsync(hbuf, state, (size_t)B_DIM * H_DIM * sizeof(float),
                    cudaMemcpyDeviceToDevice, 0);

    // Precompute all X projections (bias added here, once)
    dim3 gx(H_DIM / 64, TB / 64, 3);
    xproj_kernel<<<gx, 256>>>(inputs, W_xz, W_xr, W_xh, b_z, b_r, b_h);

    long long need = (long long)TB * I_DIM + (long long)B_DIM * H_DIM;
    int write_hfinal = ((long long)out_size >= need) ? 1 : 0;

    // Single persistent kernel for the whole recurrence
    gru_persistent<<<NB, NT>>>(W_hz, W_hr, W_hh, W_hq, b_hq, out, write_hfinal);
}

// round 10
// speedup vs baseline: 1.0713x; 1.0713x over previous
#include <cuda_runtime.h>
#include <math.h>
#include <stdint.h>

#define T_DIM 512
#define B_DIM 64
#define I_DIM 1024
#define H_DIM 2048
#define TB (T_DIM * B_DIM)
#define NB 148          // persistent grid: one block per SM
#define NT 256

typedef unsigned long long u64;

// ---- static device scratch (no allocations allowed) ----
__device__ float g_XZ[(size_t)TB * H_DIM];
__device__ float g_XR[(size_t)TB * H_DIM];
__device__ float g_XH[(size_t)TB * H_DIM];
__device__ float g_H[2][B_DIM * H_DIM];
__device__ float g_Z[B_DIM * H_DIM];
__device__ float g_RH[B_DIM * H_DIM];
__device__ unsigned g_bar_cnt;           // reset via memset each launch

// ============================================================
// Shared tile workspace: double-buffered 64x32 A tile (transposed,
// row stride 68 floats = 272B, 16B aligned) + 32x32 W tile with
// every element duplicated into both halves of a 64-bit word so the
// inner loop needs zero packing instructions.
// ============================================================
#define HS_STRIDE 68
struct __align__(16) Smem {
    float Hs[2][32][HS_STRIDE];   // [buf][k][m]
    u64   Ws2[2][32][32];         // [buf][k][n] (dup'd f32x2)
};

__device__ __forceinline__ u64 dup_f32(float f) {
    unsigned u = __float_as_uint(f);
    return (u64)u | ((u64)u << 32);
}
__device__ __forceinline__ void fma2(u64& d, u64 a, u64 b) {
    asm("fma.rn.f32x2 %0, %1, %2, %0;" : "+l"(d) : "l"(a), "l"(b));
}
__device__ __forceinline__ float2 unpack2(u64 v) {
    float2 r;
    r.x = __uint_as_float((unsigned)v);
    r.y = __uint_as_float((unsigned)(v >> 32));
    return r;
}

// ============================================================
// 64(M) x 32(N) x K fp32 GEMM tile, 256 threads, f32x2 packed FMA.
// A: M-major (64 x K, row stride K). W: K-major (K x N, row stride N).
// Thread (ty = tid>>4, tx = tid&15) owns rows ty*4..+3 (2 M-pairs),
// cols n0+tx*2, n0+tx*2+1. acc[mp][n] = f32x2 over row pair.
// Double-buffered: global loads for tile i+1 issue before compute of i.
// ============================================================
__device__ __forceinline__ void gemm_64x32(const float* __restrict__ A,
                                           const float* __restrict__ W,
                                           int K, int N, int n0,
                                           int tid, Smem& sm,
                                           u64 acc[2][2])
{
    const int tx = tid & 15;
    const int ty = tid >> 4;
    const int m  = tid >> 3;           // 0..31 (also m+32)
    const int kq = (tid & 7) * 4;      // k offset within 32-tile
    const int wk = tid >> 3;           // 0..31
    const int wn = (tid & 7) * 4;      // n offset

    acc[0][0] = acc[0][1] = acc[1][0] = acc[1][1] = 0ull;

    const float* Arow0 = A + (size_t)m * K + kq;
    const float* Arow1 = A + (size_t)(m + 32) * K + kq;
    const float* Wrow  = W + (size_t)wk * N + n0 + wn;

    // prologue: tile 0
    float4 a0 = *(const float4*)Arow0;
    float4 a1 = *(const float4*)Arow1;
    float4 w0 = *(const float4*)Wrow;

    {
        sm.Hs[0][kq + 0][m] = a0.x; sm.Hs[0][kq + 1][m] = a0.y;
        sm.Hs[0][kq + 2][m] = a0.z; sm.Hs[0][kq + 3][m] = a0.w;
        sm.Hs[0][kq + 0][m + 32] = a1.x; sm.Hs[0][kq + 1][m + 32] = a1.y;
        sm.Hs[0][kq + 2][m + 32] = a1.z; sm.Hs[0][kq + 3][m + 32] = a1.w;
        sm.Ws2[0][wk][wn + 0] = dup_f32(w0.x);
        sm.Ws2[0][wk][wn + 1] = dup_f32(w0.y);
        sm.Ws2[0][wk][wn + 2] = dup_f32(w0.z);
        sm.Ws2[0][wk][wn + 3] = dup_f32(w0.w);
    }
    __syncthreads();

    const int NIT = K / 32;
    int buf = 0;
#pragma unroll 1
    for (int it = 0; it < NIT - 1; ++it) {
        const int k0n = (it + 1) * 32;
        // issue next-tile global loads first (latency overlapped by compute)
        a0 = *(const float4*)(Arow0 + k0n);
        a1 = *(const float4*)(Arow1 + k0n);
        w0 = *(const float4*)(W + (size_t)(k0n + wk) * N + n0 + wn);

        // compute current tile
#pragma unroll
        for (int k = 0; k < 32; ++k) {
            ulonglong2 av = *(const ulonglong2*)&sm.Hs[buf][k][ty * 4];
            ulonglong2 bv = *(const ulonglong2*)&sm.Ws2[buf][k][tx * 2];
            fma2(acc[0][0], av.x, bv.x);
            fma2(acc[0][1], av.x, bv.y);
            fma2(acc[1][0], av.y, bv.x);
            fma2(acc[1][1], av.y, bv.y);
        }

        // stage next tile into the other buffer
        const int nb = buf ^ 1;
        sm.Hs[nb][kq + 0][m] = a0.x; sm.Hs[nb][kq + 1][m] = a0.y;
        sm.Hs[nb][kq + 2][m] = a0.z; sm.Hs[nb][kq + 3][m] = a0.w;
        sm.Hs[nb][kq + 0][m + 32] = a1.x; sm.Hs[nb][kq + 1][m + 32] = a1.y;
        sm.Hs[nb][kq + 2][m + 32] = a1.z; sm.Hs[nb][kq + 3][m + 32] = a1.w;
        sm.Ws2[nb][wk][wn + 0] = dup_f32(w0.x);
        sm.Ws2[nb][wk][wn + 1] = dup_f32(w0.y);
        sm.Ws2[nb][wk][wn + 2] = dup_f32(w0.z);
        sm.Ws2[nb][wk][wn + 3] = dup_f32(w0.w);
        __syncthreads();
        buf = nb;
    }
    // final tile compute
#pragma unroll
    for (int k = 0; k < 32; ++k) {
        ulonglong2 av = *(const ulonglong2*)&sm.Hs[buf][k][ty * 4];
        ulonglong2 bv = *(const ulonglong2*)&sm.Ws2[buf][k][tx * 2];
        fma2(acc[0][0], av.x, bv.x);
        fma2(acc[0][1], av.x, bv.y);
        fma2(acc[1][0], av.y, bv.x);
        fma2(acc[1][1], av.y, bv.y);
    }
    __syncthreads();
}

// ============================================================
// Precompute: g_X?[(t*B+b)][j] = X[t,b,:] @ W_x?[:,j] + b_?[j]
// grid = (H_DIM/32, TB/64, 3). Bias added HERE ONLY.
// ============================================================
__global__ void xproj_kernel(const float* __restrict__ X,
                             const float* __restrict__ Wz,
                             const float* __restrict__ Wr,
                             const float* __restrict__ Wh,
                             const float* __restrict__ bz,
                             const float* __restrict__ br,
                             const float* __restrict__ bh)
{
    __shared__ Smem sm;
    const float* W;
    const float* bias;
    float* out;
    int g = blockIdx.z;
    if (g == 0)      { W = Wz; bias = bz; out = g_XZ; }
    else if (g == 1) { W = Wr; bias = br; out = g_XR; }
    else             { W = Wh; bias = bh; out = g_XH; }

    const int n0 = blockIdx.x * 32;
    const int m0 = blockIdx.y * 64;
    const int tid = threadIdx.x;
    const int tx = tid & 15;
    const int ty = tid >> 4;

    u64 acc[2][2];
    gemm_64x32(X + (size_t)m0 * I_DIM, W, I_DIM, H_DIM, n0, tid, sm, acc);

#pragma unroll
    for (int mp = 0; mp < 2; ++mp)
#pragma unroll
        for (int n = 0; n < 2; ++n) {
            float2 v = unpack2(acc[mp][n]);
            int mrow = m0 + ty * 4 + mp * 2;
            int c = n0 + tx * 2 + n;
            float bb = bias[c];
            out[(size_t)mrow * H_DIM + c] = v.x + bb;
            out[(size_t)(mrow + 1) * H_DIM + c] = v.y + bb;
        }
}

// ============================================================
// Grid-wide barrier (monotonic counter; host resets per launch).
// ============================================================
__device__ __forceinline__ void grid_sync(unsigned target)
{
    __syncthreads();
    if (threadIdx.x == 0) {
        __threadfence();
        atomicAdd(&g_bar_cnt, 1u);
        unsigned v;
        for (;;) {
            asm volatile("ld.global.acquire.gpu.u32 %0, [%1];"
                         : "=r"(v) : "l"(&g_bar_cnt));
            if (v >= target) break;
            __nanosleep(64);
        }
    }
    __syncthreads();
}

// ============================================================
// Persistent recurrence. Per step:
//  P1 (blk 0..127): Z = sig(XZ + H@Whz); RH = sig(XR + H@Whr) * H
//  barrier
//  P2 (blk 0..63):  Hnew = Z*H + (1-Z)*tanh(XH + RH@Whh)
//     (blk 64..95): Y[t-1] = H@Whq + b_hq
//  barrier
// ============================================================
__global__ void __launch_bounds__(NT, 1)
gru_persistent(const float* __restrict__ Whz,
               const float* __restrict__ Whr,
               const float* __restrict__ Whh,
               const float* __restrict__ Whq,
               const float* __restrict__ bq,
               float* __restrict__ out,
               int write_hfinal)
{
    __shared__ Smem sm;
    const int blk = blockIdx.x;
    const int tid = threadIdx.x;
    const int tx = tid & 15;
    const int ty = tid >> 4;
    unsigned epoch = 0;
    u64 acc[2][2];

    for (int t = 0; t < T_DIM; ++t) {
        const float* Hold = g_H[t & 1];
        float* Hnew = g_H[(t + 1) & 1];

        // ---------------- P1: gates Z, R ----------------
        if (blk < 128) {
            const int gate = blk >> 6;
            const int n0 = (blk & 63) * 32;
            const float* W  = gate ? Whr  : Whz;
            const float* Xp = gate ? g_XR : g_XZ;

            gemm_64x32(Hold, W, H_DIM, H_DIM, n0, tid, sm, acc);

#pragma unroll
            for (int mp = 0; mp < 2; ++mp)
#pragma unroll
                for (int n = 0; n < 2; ++n) {
                    float2 v = unpack2(acc[mp][n]);
                    int b = ty * 4 + mp * 2;
                    int c = n0 + tx * 2 + n;
#pragma unroll
                    for (int r = 0; r < 2; ++r) {
                        float vv = (r == 0) ? v.x : v.y;
                        float x = Xp[(size_t)(t * B_DIM + b + r) * H_DIM + c] + vv;
                        float s = 1.0f / (1.0f + expf(-x));
                        if (gate) g_RH[(b + r) * H_DIM + c] = s * Hold[(b + r) * H_DIM + c];
                        else      g_Z[(b + r) * H_DIM + c]  = s;
                    }
                }
        }
        epoch++; grid_sync(epoch * NB);

        // ---------------- P2: Hnew and Y[t-1] ----------------
        if (blk < 64) {
            const int n0 = blk * 32;
            gemm_64x32(g_RH, Whh, H_DIM, H_DIM, n0, tid, sm, acc);

#pragma unroll
            for (int mp = 0; mp < 2; ++mp)
#pragma unroll
                for (int n = 0; n < 2; ++n) {
                    float2 v = unpack2(acc[mp][n]);
                    int b = ty * 4 + mp * 2;
                    int c = n0 + tx * 2 + n;
#pragma unroll
                    for (int r = 0; r < 2; ++r) {
                        float vv = (r == 0) ? v.x : v.y;
                        float ht = tanhf(g_XH[(size_t)(t * B_DIM + b + r) * H_DIM + c] + vv);
                        float z = g_Z[(b + r) * H_DIM + c];
                        Hnew[(b + r) * H_DIM + c] =
                            z * Hold[(b + r) * H_DIM + c] + (1.0f - z) * ht;
                    }
                }
        } else if (blk < 96 && t > 0) {
            const int n0 = (blk - 64) * 32;
            gemm_64x32(Hold, Whq, H_DIM, I_DIM, n0, tid, sm, acc);

#pragma unroll
            for (int mp = 0; mp < 2; ++mp)
#pragma unroll
                for (int n = 0; n < 2; ++n) {
                    float2 v = unpack2(acc[mp][n]);
                    int b = ty * 4 + mp * 2;
                    int c = n0 + tx * 2 + n;
                    float bb = bq[c];
                    out[(size_t)((t - 1) * B_DIM + b) * I_DIM + c] = v.x + bb;
                    out[(size_t)((t - 1) * B_DIM + b + 1) * I_DIM + c] = v.y + bb;
                }
        }
        epoch++; grid_sync(epoch * NB);
    }

    // ---------------- tail: Y[T-1] + optional H_final ----------------
    const float* Hfin = g_H[T_DIM & 1];
    if (blk < 32) {
        const int n0 = blk * 32;
        gemm_64x32(Hfin, Whq, H_DIM, I_DIM, n0, tid, sm, acc);
#pragma unroll
        for (int mp = 0; mp < 2; ++mp)
#pragma unroll
            for (int n = 0; n < 2; ++n) {
                float2 v = unpack2(acc[mp][n]);
                int b = ty * 4 + mp * 2;
                int c = n0 + tx * 2 + n;
                float bb = bq[c];
                out[(size_t)((T_DIM - 1) * B_DIM + b) * I_DIM + c] = v.x + bb;
                out[(size_t)((T_DIM - 1) * B_DIM + b + 1) * I_DIM + c] = v.y + bb;
            }
    } else if (blk >= 32 && blk < 64 && write_hfinal) {
        float* dst = out + (size_t)TB * I_DIM;
        int base = ((blk - 32) * NT + tid) * 16;   // 32*256*16 = 131072
#pragma unroll
        for (int v = 0; v < 4; v++) {
            *(float4*)&dst[base + v * 4] = *(const float4*)&Hfin[base + v * 4];
        }
    }
}

extern "C" void kernel_launch(void* const* d_in, const int* in_sizes, int n_in,
                              void* d_out, int out_size)
{
    (void)in_sizes; (void)n_in;
    const float* inputs = (const float*)d_in[0];
    const float* state  = (const float*)d_in[1];
    const float* W_xz   = (const float*)d_in[2];
    const float* W_hz   = (const float*)d_in[3];
    const float* b_z    = (const float*)d_in[4];
    const float* W_xr   = (const float*)d_in[5];
    const float* W_hr   = (const float*)d_in[6];
    const float* b_r    = (const float*)d_in[7];
    const float* W_xh   = (const float*)d_in[8];
    const float* W_hh   = (const float*)d_in[9];
    const float* b_h    = (const float*)d_in[10];
    const float* W_hq   = (const float*)d_in[11];
    const float* b_hq   = (const float*)d_in[12];
    float* out = (float*)d_out;

    float* hbuf = nullptr;
    cudaGetSymbolAddress((void**)&hbuf, g_H);
    unsigned* barp = nullptr;
    cudaGetSymbolAddress((void**)&barp, g_bar_cnt);

    cudaMemsetAsync(barp, 0, sizeof(unsigned), 0);
    cudaMemcpyAsync(hbuf, state, (size_t)B_DIM * H_DIM * sizeof(float),
                    cudaMemcpyDeviceToDevice, 0);

    dim3 gx(H_DIM / 32, TB / 64, 3);
    xproj_kernel<<<gx, NT>>>(inputs, W_xz, W_xr, W_xh, b_z, b_r, b_h);

    long long need = (long long)TB * I_DIM + (long long)B_DIM * H_DIM;
    int write_hfinal = ((long long)out_size >= need) ? 1 : 0;

    gru_persistent<<<NB, NT>>>(W_hz, W_hr, W_hh, W_hq, b_hq, out, write_hfinal);
}